// round 1
// baseline (speedup 1.0000x reference)
#include <cuda_runtime.h>
#include <math.h>

#define Bb 4
#define Nn 2048
#define Dd 512
#define Hh 8
#define HD 64
#define Mm (Bb * Nn)   // 8192
#define SCALE 0.125f   // 1/sqrt(64)

// ---------------- scratch (no allocation allowed) ----------------
__device__ float g_Q[(size_t)Mm * Dd];
__device__ float g_K[(size_t)Mm * Dd];
__device__ float g_V[(size_t)Mm * Dd];
__device__ float g_Hh[(size_t)Mm * Dd];
__device__ float g_Y[(size_t)Mm * Dd];

// ---------------- GEMM: C[M,N] = A[M,K] @ W[K,N] + bias (+ resid) ----------------
// BM=128, BN=128, BK=8, 256 threads, 8x8 microtile.
__global__ __launch_bounds__(256) void gemm_bias_kernel(
    const float* __restrict__ A, const float* __restrict__ W,
    const float* __restrict__ bias, const float* __restrict__ resid,
    float* __restrict__ C, int M, int N, int K)
{
    __shared__ float As[8][128];   // [k][m]
    __shared__ float Ws[8][128];   // [k][n]

    const int tid = threadIdx.x;
    const int bm = blockIdx.y;
    const int bn = blockIdx.x;
    const int tx = tid & 15;       // 0..15 -> 8 cols each
    const int ty = tid >> 4;       // 0..15 -> 8 rows each

    const float* Ablk = A + (size_t)bm * 128 * K;
    const float* Wblk = W + bn * 128;

    float acc[8][8];
#pragma unroll
    for (int i = 0; i < 8; i++)
#pragma unroll
        for (int j = 0; j < 8; j++) acc[i][j] = 0.f;

    for (int k0 = 0; k0 < K; k0 += 8) {
        // A tile: 128 rows x 8 cols. thread: r = tid/2, c = (tid&1)*4, float4.
        {
            int r = tid >> 1, c = (tid & 1) * 4;
            float4 a = *(const float4*)(Ablk + (size_t)r * K + k0 + c);
            As[c + 0][r] = a.x; As[c + 1][r] = a.y;
            As[c + 2][r] = a.z; As[c + 3][r] = a.w;
        }
        // W tile: 8 rows x 128 cols. thread: r = tid/32, c = (tid&31)*4.
        {
            int r = tid >> 5, c = (tid & 31) * 4;
            *(float4*)&Ws[r][c] = *(const float4*)(Wblk + (size_t)(k0 + r) * N + c);
        }
        __syncthreads();

#pragma unroll
        for (int kk = 0; kk < 8; kk++) {
            float a[8], b[8];
            *(float4*)&a[0] = *(const float4*)&As[kk][ty * 8];
            *(float4*)&a[4] = *(const float4*)&As[kk][ty * 8 + 4];
            *(float4*)&b[0] = *(const float4*)&Ws[kk][tx * 8];
            *(float4*)&b[4] = *(const float4*)&Ws[kk][tx * 8 + 4];
#pragma unroll
            for (int i = 0; i < 8; i++)
#pragma unroll
                for (int j = 0; j < 8; j++)
                    acc[i][j] = fmaf(a[i], b[j], acc[i][j]);
        }
        __syncthreads();
    }

    // epilogue
    const int col0 = bn * 128 + tx * 8;
#pragma unroll
    for (int i = 0; i < 8; i++) {
        int row = bm * 128 + ty * 8 + i;
        float* cp = C + (size_t)row * N + col0;
        const float* rp = resid ? (resid + (size_t)row * N + col0) : nullptr;
#pragma unroll
        for (int j = 0; j < 8; j += 4) {
            float4 o;
            o.x = acc[i][j + 0] + bias[col0 + j + 0];
            o.y = acc[i][j + 1] + bias[col0 + j + 1];
            o.z = acc[i][j + 2] + bias[col0 + j + 2];
            o.w = acc[i][j + 3] + bias[col0 + j + 3];
            if (rp) {
                float4 r4 = *(const float4*)(rp + j);
                o.x += r4.x; o.y += r4.y; o.z += r4.z; o.w += r4.w;
            }
            *(float4*)(cp + j) = o;
        }
    }
}

// ---------------- masked flash attention ----------------
// grid: (N/128, H, B), 128 threads; one thread = one query row.
__global__ __launch_bounds__(128) void attn_kernel(
    const float* __restrict__ Q, const float* __restrict__ K,
    const float* __restrict__ V, const int* __restrict__ adj,
    float* __restrict__ O)
{
    __shared__ float Ksm[64][64];
    __shared__ float Vsm[64][64];

    const int tid = threadIdx.x;
    const int h = blockIdx.y;
    const int b = blockIdx.z;
    const int qi = blockIdx.x * 128 + tid;

    const float* qptr = Q + ((size_t)b * Nn + qi) * Dd + h * HD;
    float4 q4[16];
#pragma unroll
    for (int i = 0; i < 16; i++) q4[i] = ((const float4*)qptr)[i];

    float o[64];
#pragma unroll
    for (int d = 0; d < 64; d++) o[d] = 0.f;
    float m = -INFINITY, l = 0.f;

    const int* adjRow = adj + ((size_t)b * Nn + qi) * Nn;

    for (int k0 = 0; k0 < Nn; k0 += 64) {
        __syncthreads();
        // load K/V tiles: 64 keys x 64 dims
        {
            int c = (tid & 15) * 4;
            for (int j = tid >> 4; j < 64; j += 8) {
                const size_t base = ((size_t)b * Nn + k0 + j) * Dd + h * HD + c;
                *(float4*)&Ksm[j][c] = *(const float4*)(K + base);
                *(float4*)&Vsm[j][c] = *(const float4*)(V + base);
            }
        }
        __syncthreads();

#pragma unroll 1
        for (int j0 = 0; j0 < 64; j0 += 4) {
            int4 msk = *(const int4*)(adjRow + k0 + j0);
            int mm[4] = {msk.x, msk.y, msk.z, msk.w};
#pragma unroll
            for (int u = 0; u < 4; u++) {
                if (!mm[u]) continue;
                const int j = j0 + u;
                const float4* krow = (const float4*)Ksm[j];
                float s = 0.f;
#pragma unroll
                for (int kk = 0; kk < 16; kk++) {
                    float4 kv = krow[kk];
                    s = fmaf(q4[kk].x, kv.x, s);
                    s = fmaf(q4[kk].y, kv.y, s);
                    s = fmaf(q4[kk].z, kv.z, s);
                    s = fmaf(q4[kk].w, kv.w, s);
                }
                s *= SCALE;
                if (s > m) {
                    float c = __expf(m - s);   // exp(-inf)=0 on first hit
                    l *= c;
#pragma unroll
                    for (int d = 0; d < 64; d++) o[d] *= c;
                    m = s;
                }
                float p = __expf(s - m);
                l += p;
                const float4* vrow = (const float4*)Vsm[j];
#pragma unroll
                for (int kk = 0; kk < 16; kk++) {
                    float4 vv = vrow[kk];
                    o[4 * kk + 0] = fmaf(p, vv.x, o[4 * kk + 0]);
                    o[4 * kk + 1] = fmaf(p, vv.y, o[4 * kk + 1]);
                    o[4 * kk + 2] = fmaf(p, vv.z, o[4 * kk + 2]);
                    o[4 * kk + 3] = fmaf(p, vv.w, o[4 * kk + 3]);
                }
            }
        }
    }

    const float inv = 1.f / l;
    float* optr = O + ((size_t)b * Nn + qi) * Dd + h * HD;
#pragma unroll
    for (int kk = 0; kk < 16; kk++) {
        float4 r;
        r.x = o[4 * kk + 0] * inv;
        r.y = o[4 * kk + 1] * inv;
        r.z = o[4 * kk + 2] * inv;
        r.w = o[4 * kk + 3] * inv;
        ((float4*)optr)[kk] = r;
    }
}

// ---------------- LayerNorm: one block per row ----------------
__global__ __launch_bounds__(128) void ln_kernel(
    const float* __restrict__ Y, const float* __restrict__ gamma,
    const float* __restrict__ beta, float* __restrict__ out)
{
    __shared__ float sbuf[4];
    __shared__ float smu, srstd;
    const int tid = threadIdx.x;
    const int row = blockIdx.x;
    const float* y = Y + (size_t)row * Dd;

    float4 v = ((const float4*)y)[tid];
    float sum = v.x + v.y + v.z + v.w;
    // block reduce (128 threads, 4 warps)
    int lane = tid & 31, wid = tid >> 5;
#pragma unroll
    for (int off = 16; off > 0; off >>= 1) sum += __shfl_xor_sync(0xffffffffu, sum, off);
    if (lane == 0) sbuf[wid] = sum;
    __syncthreads();
    if (tid == 0) smu = (sbuf[0] + sbuf[1] + sbuf[2] + sbuf[3]) * (1.f / Dd);
    __syncthreads();
    float mu = smu;

    float dx = v.x - mu, dy = v.y - mu, dz = v.z - mu, dw = v.w - mu;
    float sq = dx * dx + dy * dy + dz * dz + dw * dw;
#pragma unroll
    for (int off = 16; off > 0; off >>= 1) sq += __shfl_xor_sync(0xffffffffu, sq, off);
    __syncthreads();
    if (lane == 0) sbuf[wid] = sq;
    __syncthreads();
    if (tid == 0) {
        float var = (sbuf[0] + sbuf[1] + sbuf[2] + sbuf[3]) * (1.f / Dd);
        srstd = rsqrtf(var + 1e-5f);
    }
    __syncthreads();
    float rstd = srstd;

    int c = tid * 4;
    float4 g = *(const float4*)(gamma + c);
    float4 be = *(const float4*)(beta + c);
    float4 r;
    r.x = dx * rstd * g.x + be.x;
    r.y = dy * rstd * g.y + be.y;
    r.z = dz * rstd * g.z + be.z;
    r.w = dw * rstd * g.w + be.w;
    ((float4*)(out + (size_t)row * Dd))[tid] = r;
}

// ---------------- launch ----------------
extern "C" void kernel_launch(void* const* d_in, const int* in_sizes, int n_in,
                              void* d_out, int out_size)
{
    const float* x     = (const float*)d_in[0];
    const int*   adj   = (const int*)d_in[1];
    const float* Wq    = (const float*)d_in[2];
    const float* bq    = (const float*)d_in[3];
    const float* Wk    = (const float*)d_in[4];
    const float* bk    = (const float*)d_in[5];
    const float* Wv    = (const float*)d_in[6];
    const float* bv    = (const float*)d_in[7];
    const float* Wo    = (const float*)d_in[8];
    const float* bo    = (const float*)d_in[9];
    const float* gamma = (const float*)d_in[10];
    const float* beta  = (const float*)d_in[11];
    float* out = (float*)d_out;

    float *Qb, *Kb, *Vb, *Hb, *Yb;
    cudaGetSymbolAddress((void**)&Qb, g_Q);
    cudaGetSymbolAddress((void**)&Kb, g_K);
    cudaGetSymbolAddress((void**)&Vb, g_V);
    cudaGetSymbolAddress((void**)&Hb, g_Hh);
    cudaGetSymbolAddress((void**)&Yb, g_Y);

    dim3 ggrid(Dd / 128, Mm / 128);   // (4, 64)
    gemm_bias_kernel<<<ggrid, 256>>>(x, Wq, bq, nullptr, Qb, Mm, Dd, Dd);
    gemm_bias_kernel<<<ggrid, 256>>>(x, Wk, bk, nullptr, Kb, Mm, Dd, Dd);
    gemm_bias_kernel<<<ggrid, 256>>>(x, Wv, bv, nullptr, Vb, Mm, Dd, Dd);

    dim3 agrid(Nn / 128, Hh, Bb);     // (16, 8, 4)
    attn_kernel<<<agrid, 128>>>(Qb, Kb, Vb, adj, Hb);

    gemm_bias_kernel<<<ggrid, 256>>>(Hb, Wo, bo, x, Yb, Mm, Dd, Dd);

    ln_kernel<<<Mm, 128>>>(Yb, gamma, beta, out);
}